// round 15
// baseline (speedup 1.0000x reference)
#include <cuda_runtime.h>
#include <math.h>

// Problem constants
#define BATCH 2048
#define DIM   3072
#define NCLS  10
#define MDIM  9
#define TPB   512
#define NWARP 16
#define NGRP  4                // 4 warp-groups of 4 warps per block
#define GRID  148
#define NWORK (GRID - 1)       // blocks 1..147 do GEMV work
#define NTASK (BATCH / 4)      // 512 quad-tasks, 4 samples each
#define PAD   3084             // Wt row stride
#define SCALE 0.999999f
#define NSTAB 1e-7f
#define EPS2  0.01f

#define WT_BYTES (NCLS * PAD * 4)   // 123360

__device__ __align__(16) float g_G[NCLS * NCLS];  // W^T W from block 0
__device__ float        g_norm[BATCH];
__device__ unsigned int g_flag;      // zero-init; set by block 0, reset by tail
__device__ unsigned int g_count;     // zero-init; reset in-kernel

// group-private barrier: 4 warps (128 threads), ids 1..4
__device__ __forceinline__ void grp_bar(int g) {
    asm volatile("bar.sync %0, %1;" :: "r"(g + 1), "r"(128) : "memory");
}

// ---------------------------------------------------------------------------
// R15: dedicated G-block (block 0) as in R14, but workers stage g_G into
// SHARED memory with one 25-lane float4 __ldcg copy per epilogue warp, so
// the epilogue itself is the known-good all-LDS R13 code.  Workers drop the
// ~725-instr redundant G-stage without inheriting R14's global-load chain.
// ---------------------------------------------------------------------------
__global__ void __launch_bounds__(TPB, 1)
k_fused(const float* __restrict__ data,
        const float* __restrict__ W,
        const float* __restrict__ b,
        float* __restrict__ out) {
    extern __shared__ float Wt[];                 // [NCLS][PAD]
    __shared__ __align__(16) float Gs[NCLS * NCLS];
    __shared__ float shop[NWARP][56];             // G staging (block 0 only)
    __shared__ float scr[NGRP][4][8][4][NCLS];    // grp, warp, lanegrp, sample
    __shared__ float shp[NWARP][NCLS];
    __shared__ float sha[NWARP][MDIM];
    __shared__ float shb[NWARP][MDIM];
    __shared__ float shg[NWARP][NCLS];
    __shared__ float red[TPB];
    __shared__ unsigned int s_rank;

    const int tid   = threadIdx.x;
    const int lane  = tid & 31;
    const int wid   = tid >> 5;
    const int grp   = wid >> 2;    // 0..3
    const int wrole = wid & 3;     // quarter of DIM this warp covers
    const int bid   = blockIdx.x;

    // blocks 1..147 own tasks; block 0 owns none
    const int qtask   = (bid - 1) + NWORK * grp;
    const bool active = (bid >= 1) && (qtask < NTASK);
    const int d4base  = wrole * 192 + lane;        // 192 float4 per quarter
    const float4* xq0 = active
        ? (const float4*)(data + (size_t)(4 * qtask) * DIM) + d4base : 0;
    const float4* xq1 = active ? xq0 + DIM / 4 : 0;
    const float4* xq2 = active ? xq1 + DIM / 4 : 0;
    const float4* xq3 = active ? xq2 + DIM / 4 : 0;

    float4 ba[2][4];    // [buf][sample]

    // ---- stage 1: batched W load (15 independent LDG.128)
    float4 wv[15];
    {
        const float4* W4 = (const float4*)W;
        #pragma unroll
        for (int i = 0; i < 15; i++)
            wv[i] = W4[tid + i * TPB];
    }
    // ---- prefetch first x float4 for all 4 samples
    if (active) {
        ba[0][0] = xq0[0];
        ba[0][1] = xq1[0];
        ba[0][2] = xq2[0];
        ba[0][3] = xq3[0];
    }
    // ---- scatter-store transpose
    {
        int d = (4 * tid) / NCLS;
        int l = (4 * tid) % NCLS;
        #pragma unroll
        for (int i = 0; i < 15; i++) {
            const float4 v = wv[i];
            int dd = d, ll = l;
            Wt[ll * PAD + dd] = v.x;
            if (++ll == NCLS) { ll = 0; dd++; }
            Wt[ll * PAD + dd] = v.y;
            if (++ll == NCLS) { ll = 0; dd++; }
            Wt[ll * PAD + dd] = v.z;
            if (++ll == NCLS) { ll = 0; dd++; }
            Wt[ll * PAD + dd] = v.w;
            d += 204; l += 8;                 // e += 2048
            if (l >= NCLS) { l -= NCLS; d++; }
        }
    }
    __syncthreads();

    // ---- stage 2 (block 0 ONLY): G = W^T W -> global, fence, flag
    if (bid == 0) {
        float op[55];
        #pragma unroll
        for (int e = 0; e < 55; e++) op[e] = 0.f;
        #pragma unroll
        for (int i = 0; i < DIM / TPB; i++) {
            const int d = tid + i * TPB;
            float wrow[NCLS];
            #pragma unroll
            for (int l = 0; l < NCLS; l++) wrow[l] = Wt[l * PAD + d];
            int e = 0;
            #pragma unroll
            for (int i2 = 0; i2 < NCLS; i2++)
                #pragma unroll
                for (int j2 = i2; j2 < NCLS; j2++)
                    op[e++] += wrow[i2] * wrow[j2];
        }
        #pragma unroll
        for (int e = 0; e < 55; e++) {
            #pragma unroll
            for (int off = 16; off; off >>= 1)
                op[e] += __shfl_xor_sync(0xFFFFFFFFu, op[e], off);
        }
        if (lane == 0) {
            #pragma unroll
            for (int e = 0; e < 55; e++) shop[wid][e] = op[e];
        }
        __syncthreads();
        if (tid < 55) {
            float t = 0.f;
            #pragma unroll
            for (int w = 0; w < NWARP; w++) t += shop[w][tid];
            int e = tid, i = 0;
            while (e >= NCLS - i) { e -= NCLS - i; i++; }
            const int j = i + e;
            g_G[i * NCLS + j] = t;
            g_G[j * NCLS + i] = t;
        }
        __syncthreads();
        if (tid == 0) {
            __threadfence();                      // publish g_G
            *(volatile unsigned int*)&g_flag = 1u;
        }
    }

    // ---- main: 4-warp group GEMV over 4 samples + one epilogue per warp
    if (active) {
        const float bl = (lane < NCLS) ? b[lane] : 0.f;

        float acc[4][NCLS];
        #pragma unroll
        for (int s = 0; s < 4; s++)
            #pragma unroll
            for (int l = 0; l < NCLS; l++) acc[s][l] = 0.f;

        #pragma unroll
        for (int j = 0; j < 6; j++) {        // 6 chunks of 32 float4
            const int cur = j & 1, nxt = cur ^ 1;
            if (j < 5) {
                const int o = 32 * (j + 1);
                ba[nxt][0] = xq0[o];
                ba[nxt][1] = xq1[o];
                ba[nxt][2] = xq2[o];
                ba[nxt][3] = xq3[o];
            }
            const int d4 = d4base + 32 * j;
            #pragma unroll
            for (int l = 0; l < NCLS; l++) {
                const float4 w = *(const float4*)(Wt + l * PAD + 4 * d4);
                #pragma unroll
                for (int s = 0; s < 4; s++) {
                    acc[s][l] += ba[cur][s].x * w.x + ba[cur][s].y * w.y
                               + ba[cur][s].z * w.z + ba[cur][s].w * w.w;
                }
            }
        }

        // 2-step butterfly -> lanes 0..7 hold 4-lane group sums
        #pragma unroll
        for (int s = 0; s < 4; s++)
            #pragma unroll
            for (int l = 0; l < NCLS; l++) {
                #pragma unroll
                for (int off = 16; off >= 8; off >>= 1)
                    acc[s][l] +=
                        __shfl_xor_sync(0xFFFFFFFFu, acc[s][l], off);
            }
        if (lane < 8) {
            #pragma unroll
            for (int s = 0; s < 4; s++)
                #pragma unroll
                for (int l = 0; l < NCLS; l++)
                    scr[grp][wrole][lane][s][l] = acc[s][l];
        }
        grp_bar(grp);    // combine partials across the 4-warp group

        // ---- wait for block 0's G (normally already published), then stage
        // it into SHARED memory once per warp (redundant identical writes
        // across warps are benign).  __ldcg avoids any L1 staleness issue.
        while (*(volatile unsigned int*)&g_flag == 0u) { }
        __threadfence();
        if (lane < 25) {
            const float4 gv = __ldcg((const float4*)g_G + lane);
            *((float4*)Gs + lane) = gv;
        }
        __syncwarp();

        // ---- epilogue: warp `wrole` handles sample 4*qtask + wrole
        // (identical to R13 — all G reads from smem)
        {
            const int sE = wrole;
            float logit = -1e30f;
            if (lane < NCLS) {
                float v0 = bl, v1 = 0.f;
                #pragma unroll
                for (int w4 = 0; w4 < 4; w4++) {
                    #pragma unroll
                    for (int g = 0; g < 8; g += 2) {
                        v0 += scr[grp][w4][g][sE][lane];
                        v1 += scr[grp][w4][g + 1][sE][lane];
                    }
                }
                logit = v0 + v1;
            }
            // softmax over lanes 0..9 (16-lane butterfly; lanes 16..31 get
            // correct scalars via the factor broadcast below)
            float mval = logit;
            #pragma unroll
            for (int off = 8; off; off >>= 1)
                mval = fmaxf(mval, __shfl_xor_sync(0xFFFFFFFFu, mval, off));
            float e = (lane < NCLS) ? expf(logit - mval) : 0.f;
            float ssum = e;
            #pragma unroll
            for (int off = 8; off; off >>= 1)
                ssum += __shfl_xor_sync(0xFFFFFFFFu, ssum, off);
            const float p  = e / ssum;
            const float q  = p * SCALE + NSTAB;
            const float nc = sqrtf(q);
            float ncs = (lane < NCLS) ? nc : 0.f;
            #pragma unroll
            for (int off = 8; off; off >>= 1)
                ncs += __shfl_xor_sync(0xFFFFFFFFu, ncs, off);
            const float nc9 = __shfl_sync(0xFFFFFFFFu, nc, 9);
            const float p9  = __shfl_sync(0xFFFFFFFFu, p, 9);
            const float denom = 1.f - nc9;
            float arg = ncs * 0.3162277660168379f;   // 1/sqrt(10)
            arg = fminf(arg, 1.f);
            const float delta  = 2.f * acosf(arg);
            float factor = delta * delta / (4.f * denom * denom * EPS2);
            factor = __shfl_sync(0xFFFFFFFFu, factor, 0);

            if (lane < NCLS) shp[wid][lane] = p;
            if (lane < MDIM) {
                sha[wid][lane] = SCALE * p / (nc * denom);
                shb[wid][lane] = SCALE * nc * p9 / (nc9 * denom * denom);
            }
            __syncwarp();
            if (lane < NCLS) {
                float gg = 0.f;
                #pragma unroll
                for (int k2 = 0; k2 < NCLS; k2++)
                    gg += Gs[lane * NCLS + k2] * shp[wid][k2];
                shg[wid][lane] = gg;
            }
            __syncwarp();
            float sdot = 0.f;
            #pragma unroll
            for (int k2 = 0; k2 < NCLS; k2++)
                sdot += shp[wid][k2] * shg[wid][k2];
            const float tval = shg[wid][MDIM];
            const float r    = Gs[MDIM * NCLS + MDIM];

            // M = A G A^T via rank structure (81 entries over 32 lanes)
            float ssq = 0.f;
            #pragma unroll
            for (int rep = 0; rep < 3; rep++) {
                const int e2 = lane + rep * 32;
                if (e2 < MDIM * MDIM) {
                    const int i = e2 / MDIM, j = e2 % MDIM;
                    const float ai = sha[wid][i], aj = sha[wid][j];
                    const float bi = shb[wid][i], bj = shb[wid][j];
                    const float gi = -(ai + bi), gj = -(aj + bj);
                    const float ggi = shg[wid][i], ggj = shg[wid][j];
                    float Mij = ai * aj * Gs[i * NCLS + j]
                              + ai * bj * Gs[i * NCLS + MDIM]
                              + bi * aj * Gs[j * NCLS + MDIM]
                              + ai * gj * ggi
                              + gi * aj * ggj
                              + bi * bj * r
                              + (bi * gj + gi * bj) * tval
                              + gi * gj * sdot;
                    const float v2 = Mij - ((i == j) ? factor : 0.f);
                    ssq += v2 * v2;
                }
            }
            #pragma unroll
            for (int off = 16; off; off >>= 1)
                ssq += __shfl_xor_sync(0xFFFFFFFFu, ssq, off);
            if (lane == 0) g_norm[4 * qtask + sE] = sqrtf(ssq);
        }
    }

    // ---- fused final reduction: last block to arrive does it
    __syncthreads();
    if (tid == 0) {
        __threadfence();
        s_rank = atomicAdd(&g_count, 1u);
    }
    __syncthreads();
    if (s_rank == GRID - 1) {
        __threadfence();
        float t0, t1, t2, t3;          // 4 independent loads (MLP)
        t0 = g_norm[tid];
        t1 = g_norm[tid + TPB];
        t2 = g_norm[tid + 2 * TPB];
        t3 = g_norm[tid + 3 * TPB];
        red[tid] = (t0 + t1) + (t2 + t3);
        __syncthreads();
        #pragma unroll
        for (int off = TPB / 2; off; off >>= 1) {
            if (tid < off) red[tid] += red[tid + off];
            __syncthreads();
        }
        if (tid == 0) {
            out[0] = red[0] * (1.0f / (BATCH * 81.0f));
            g_count = 0;
            *(volatile unsigned int*)&g_flag = 0u;   // reset for replay
        }
    }
}

// ---------------------------------------------------------------------------
extern "C" void kernel_launch(void* const* d_in, const int* in_sizes, int n_in,
                              void* d_out, int out_size) {
    const float* data = 0;
    const float* W    = 0;
    const float* b    = 0;
    for (int i = 0; i < n_in; i++) {
        if (in_sizes[i] == BATCH * DIM)      data = (const float*)d_in[i];
        else if (in_sizes[i] == DIM * NCLS)  W    = (const float*)d_in[i];
        else if (in_sizes[i] == NCLS)        b    = (const float*)d_in[i];
    }
    float* out = (float*)d_out;

    cudaFuncSetAttribute(k_fused,
                         cudaFuncAttributeMaxDynamicSharedMemorySize,
                         WT_BYTES);
    k_fused<<<GRID, TPB, WT_BYTES>>>(data, W, b, out);
}

// round 17
// speedup vs baseline: 1.5621x; 1.5621x over previous
#include <cuda_runtime.h>
#include <math.h>

// Problem constants
#define BATCH 2048
#define DIM   3072
#define NCLS  10
#define MDIM  9
#define TPB   512
#define NWARP 16
#define NGRP  4                // 4 warp-groups of 4 warps per block
#define GRID  148
#define NTASK (BATCH / 4)      // 512 quad-tasks, 4 samples each
#define PAD   3084             // Wt row stride (floats; 16B-multiple)
#define SCALE 0.999999f
#define NSTAB 1e-7f
#define EPS2  0.01f

#define WT_BYTES (NCLS * PAD * 4)   // 123360

__device__ float        g_norm[BATCH];
__device__ unsigned int g_count;     // zero-init; reset in-kernel

// group-private barrier: 4 warps (128 threads), ids 1..4
__device__ __forceinline__ void grp_bar(int g) {
    asm volatile("bar.sync %0, %1;" :: "r"(g + 1), "r"(128) : "memory");
}

// packed f32x2 FMA: acc += a * b (elementwise on (lo,hi) pairs)
__device__ __forceinline__ void fma2(unsigned long long& acc,
                                     unsigned long long a,
                                     unsigned long long b) {
    asm("fma.rn.f32x2 %0, %1, %2, %0;" : "+l"(acc) : "l"(a), "l"(b));
}
// unpack (lo,hi) and horizontal-add
__device__ __forceinline__ float upk(unsigned long long v) {
    float lo, hi;
    asm("mov.b64 {%0, %1}, %2;" : "=f"(lo), "=f"(hi) : "l"(v));
    return lo + hi;
}

// ---------------------------------------------------------------------------
// R16 resubmit (R16 bench was an infra failure): R13 structure (per-block G,
// quad-task / quad-warp groups) with the GEMV inner loop converted to packed
// fma.rn.f32x2 over dim-pairs: both operands come naturally packed from 16B
// loads viewed as ulonglong2, so the fma-pipe instruction count halves with
// zero packing MOVs.  x is single-buffered (acc2 doubles register use; x is
// L2-resident on graph replays).
// ---------------------------------------------------------------------------
__global__ void __launch_bounds__(TPB, 1)
k_fused(const float* __restrict__ data,
        const float* __restrict__ W,
        const float* __restrict__ b,
        float* __restrict__ out) {
    extern __shared__ float Wt[];                 // [NCLS][PAD]
    __shared__ float Gs[NCLS * NCLS];
    __shared__ float shop[NWARP][56];             // G staging
    __shared__ float scr[NGRP][4][8][4][NCLS];    // grp, warp, lanegrp, sample
    __shared__ float shp[NWARP][NCLS];
    __shared__ float sha[NWARP][MDIM];
    __shared__ float shb[NWARP][MDIM];
    __shared__ float shg[NWARP][NCLS];
    __shared__ float red[TPB];
    __shared__ unsigned int s_rank;

    const int tid   = threadIdx.x;
    const int lane  = tid & 31;
    const int wid   = tid >> 5;
    const int grp   = wid >> 2;    // 0..3
    const int wrole = wid & 3;     // quarter of DIM this warp covers

    const int qtask   = blockIdx.x + gridDim.x * grp;
    const bool active = (qtask < NTASK);
    const int d4base  = wrole * 192 + lane;        // 16B-units into sample
    const ulonglong2* xq0 = active
        ? (const ulonglong2*)(data + (size_t)(4 * qtask) * DIM) + d4base : 0;
    const ulonglong2* xq1 = active ? xq0 + DIM / 4 : 0;
    const ulonglong2* xq2 = active ? xq1 + DIM / 4 : 0;
    const ulonglong2* xq3 = active ? xq2 + DIM / 4 : 0;

    // ---- stage 1: batched W load (15 independent LDG.128)
    float4 wv[15];
    {
        const float4* W4 = (const float4*)W;
        #pragma unroll
        for (int i = 0; i < 15; i++)
            wv[i] = W4[tid + i * TPB];
    }
    // ---- scatter-store transpose
    {
        int d = (4 * tid) / NCLS;
        int l = (4 * tid) % NCLS;
        #pragma unroll
        for (int i = 0; i < 15; i++) {
            const float4 v = wv[i];
            int dd = d, ll = l;
            Wt[ll * PAD + dd] = v.x;
            if (++ll == NCLS) { ll = 0; dd++; }
            Wt[ll * PAD + dd] = v.y;
            if (++ll == NCLS) { ll = 0; dd++; }
            Wt[ll * PAD + dd] = v.z;
            if (++ll == NCLS) { ll = 0; dd++; }
            Wt[ll * PAD + dd] = v.w;
            d += 204; l += 8;                 // e += 2048
            if (l >= NCLS) { l -= NCLS; d++; }
        }
    }
    __syncthreads();

    // ---- stage 2: G = W^T W (upper triangle) from smem rows (R13-identical)
    {
        float op[55];
        #pragma unroll
        for (int e = 0; e < 55; e++) op[e] = 0.f;
        #pragma unroll
        for (int i = 0; i < DIM / TPB; i++) {
            const int d = tid + i * TPB;
            float wrow[NCLS];
            #pragma unroll
            for (int l = 0; l < NCLS; l++) wrow[l] = Wt[l * PAD + d];
            int e = 0;
            #pragma unroll
            for (int i2 = 0; i2 < NCLS; i2++)
                #pragma unroll
                for (int j2 = i2; j2 < NCLS; j2++)
                    op[e++] += wrow[i2] * wrow[j2];
        }
        #pragma unroll
        for (int e = 0; e < 55; e++) {
            #pragma unroll
            for (int off = 16; off; off >>= 1)
                op[e] += __shfl_xor_sync(0xFFFFFFFFu, op[e], off);
        }
        if (lane == 0) {
            #pragma unroll
            for (int e = 0; e < 55; e++) shop[wid][e] = op[e];
        }
    }
    __syncthreads();
    if (tid < 55) {
        float t = 0.f;
        #pragma unroll
        for (int w = 0; w < NWARP; w++) t += shop[w][tid];
        int e = tid, i = 0;
        while (e >= NCLS - i) { e -= NCLS - i; i++; }
        const int j = i + e;
        Gs[i * NCLS + j] = t;
        Gs[j * NCLS + i] = t;
    }
    __syncthreads();

    // ---- main: 4-warp group GEMV (f32x2) over 4 samples + 1 epilogue/warp
    if (active) {
        const float bl = (lane < NCLS) ? b[lane] : 0.f;

        unsigned long long acc2[4][NCLS];     // packed (even,odd) dim partials
        #pragma unroll
        for (int s = 0; s < 4; s++)
            #pragma unroll
            for (int l = 0; l < NCLS; l++) acc2[s][l] = 0ull;

        #pragma unroll
        for (int j = 0; j < 6; j++) {         // 6 chunks; 1 x 16B/lane/sample
            ulonglong2 xv[4];
            xv[0] = xq0[32 * j];
            xv[1] = xq1[32 * j];
            xv[2] = xq2[32 * j];
            xv[3] = xq3[32 * j];
            const int d4 = d4base + 32 * j;
            #pragma unroll
            for (int l = 0; l < NCLS; l++) {
                const ulonglong2 w2 =
                    *(const ulonglong2*)(Wt + l * PAD + 4 * d4);
                #pragma unroll
                for (int s = 0; s < 4; s++) {
                    fma2(acc2[s][l], w2.x, xv[s].x);
                    fma2(acc2[s][l], w2.y, xv[s].y);
                }
            }
        }

        // per-sample: unpack, 2-step butterfly, stage to scr
        #pragma unroll
        for (int s = 0; s < 4; s++) {
            float a[NCLS];
            #pragma unroll
            for (int l = 0; l < NCLS; l++) a[l] = upk(acc2[s][l]);
            #pragma unroll
            for (int l = 0; l < NCLS; l++) {
                #pragma unroll
                for (int off = 16; off >= 8; off >>= 1)
                    a[l] += __shfl_xor_sync(0xFFFFFFFFu, a[l], off);
            }
            if (lane < 8) {
                #pragma unroll
                for (int l = 0; l < NCLS; l++)
                    scr[grp][wrole][lane][s][l] = a[l];
            }
        }
        grp_bar(grp);    // combine partials across the 4-warp group

        // ---- epilogue: warp `wrole` handles sample 4*qtask + wrole
        {
            const int sE = wrole;
            float logit = -1e30f;
            if (lane < NCLS) {
                float v0 = bl, v1 = 0.f;
                #pragma unroll
                for (int w4 = 0; w4 < 4; w4++) {
                    #pragma unroll
                    for (int g = 0; g < 8; g += 2) {
                        v0 += scr[grp][w4][g][sE][lane];
                        v1 += scr[grp][w4][g + 1][sE][lane];
                    }
                }
                logit = v0 + v1;
            }
            // softmax over lanes 0..9 (16-lane butterfly; lanes 16..31 get
            // correct scalars via the factor broadcast below)
            float mval = logit;
            #pragma unroll
            for (int off = 8; off; off >>= 1)
                mval = fmaxf(mval, __shfl_xor_sync(0xFFFFFFFFu, mval, off));
            float e = (lane < NCLS) ? expf(logit - mval) : 0.f;
            float ssum = e;
            #pragma unroll
            for (int off = 8; off; off >>= 1)
                ssum += __shfl_xor_sync(0xFFFFFFFFu, ssum, off);
            const float p  = e / ssum;
            const float q  = p * SCALE + NSTAB;
            const float nc = sqrtf(q);
            float ncs = (lane < NCLS) ? nc : 0.f;
            #pragma unroll
            for (int off = 8; off; off >>= 1)
                ncs += __shfl_xor_sync(0xFFFFFFFFu, ncs, off);
            const float nc9 = __shfl_sync(0xFFFFFFFFu, nc, 9);
            const float p9  = __shfl_sync(0xFFFFFFFFu, p, 9);
            const float denom = 1.f - nc9;
            float arg = ncs * 0.3162277660168379f;   // 1/sqrt(10)
            arg = fminf(arg, 1.f);
            const float delta  = 2.f * acosf(arg);
            float factor = delta * delta / (4.f * denom * denom * EPS2);
            factor = __shfl_sync(0xFFFFFFFFu, factor, 0);

            if (lane < NCLS) shp[wid][lane] = p;
            if (lane < MDIM) {
                sha[wid][lane] = SCALE * p / (nc * denom);
                shb[wid][lane] = SCALE * nc * p9 / (nc9 * denom * denom);
            }
            __syncwarp();
            if (lane < NCLS) {
                float gg = 0.f;
                #pragma unroll
                for (int k2 = 0; k2 < NCLS; k2++)
                    gg += Gs[lane * NCLS + k2] * shp[wid][k2];
                shg[wid][lane] = gg;
            }
            __syncwarp();
            float sdot = 0.f;
            #pragma unroll
            for (int k2 = 0; k2 < NCLS; k2++)
                sdot += shp[wid][k2] * shg[wid][k2];
            const float tval = shg[wid][MDIM];
            const float r    = Gs[MDIM * NCLS + MDIM];

            // M = A G A^T via rank structure (81 entries over 32 lanes)
            float ssq = 0.f;
            #pragma unroll
            for (int rep = 0; rep < 3; rep++) {
                const int e2 = lane + rep * 32;
                if (e2 < MDIM * MDIM) {
                    const int i = e2 / MDIM, j = e2 % MDIM;
                    const float ai = sha[wid][i], aj = sha[wid][j];
                    const float bi = shb[wid][i], bj = shb[wid][j];
                    const float gi = -(ai + bi), gj = -(aj + bj);
                    const float ggi = shg[wid][i], ggj = shg[wid][j];
                    float Mij = ai * aj * Gs[i * NCLS + j]
                              + ai * bj * Gs[i * NCLS + MDIM]
                              + bi * aj * Gs[j * NCLS + MDIM]
                              + ai * gj * ggi
                              + gi * aj * ggj
                              + bi * bj * r
                              + (bi * gj + gi * bj) * tval
                              + gi * gj * sdot;
                    const float v2 = Mij - ((i == j) ? factor : 0.f);
                    ssq += v2 * v2;
                }
            }
            #pragma unroll
            for (int off = 16; off; off >>= 1)
                ssq += __shfl_xor_sync(0xFFFFFFFFu, ssq, off);
            if (lane == 0) g_norm[4 * qtask + sE] = sqrtf(ssq);
        }
    }

    // ---- fused final reduction: last block to arrive does it
    __syncthreads();
    if (tid == 0) {
        __threadfence();
        s_rank = atomicAdd(&g_count, 1u);
    }
    __syncthreads();
    if (s_rank == GRID - 1) {
        __threadfence();
        float t0, t1, t2, t3;          // 4 independent loads (MLP)
        t0 = g_norm[tid];
        t1 = g_norm[tid + TPB];
        t2 = g_norm[tid + 2 * TPB];
        t3 = g_norm[tid + 3 * TPB];
        red[tid] = (t0 + t1) + (t2 + t3);
        __syncthreads();
        #pragma unroll
        for (int off = TPB / 2; off; off >>= 1) {
            if (tid < off) red[tid] += red[tid + off];
            __syncthreads();
        }
        if (tid == 0) {
            out[0] = red[0] * (1.0f / (BATCH * 81.0f));
            g_count = 0;
        }
    }
}

// ---------------------------------------------------------------------------
extern "C" void kernel_launch(void* const* d_in, const int* in_sizes, int n_in,
                              void* d_out, int out_size) {
    const float* data = 0;
    const float* W    = 0;
    const float* b    = 0;
    for (int i = 0; i < n_in; i++) {
        if (in_sizes[i] == BATCH * DIM)      data = (const float*)d_in[i];
        else if (in_sizes[i] == DIM * NCLS)  W    = (const float*)d_in[i];
        else if (in_sizes[i] == NCLS)        b    = (const float*)d_in[i];
    }
    float* out = (float*)d_out;

    cudaFuncSetAttribute(k_fused,
                         cudaFuncAttributeMaxDynamicSharedMemorySize,
                         WT_BYTES);
    k_fused<<<GRID, TPB, WT_BYTES>>>(data, W, b, out);
}